// round 2
// baseline (speedup 1.0000x reference)
#include <cuda_runtime.h>
#include <cstdint>

// Problem constants (fixed by reference: POOL=100, N_TASKS=5 -> F_END=20)
#define KEY_D   768
#define EMB_D   768
#define P_FEAT  9216      // EMB_D * HEADS
#define E_P_LEN 8
#define FEND    20
#define TOPKN   10
#define EPSV    1e-12f

// Kernel-2 tiling
#define DC  128           // d-chunk per block
#define QB  64            // queries per block
#define K2_THREADS 256    // 8 query-groups (warps) x 32 d-lanes

// Dense gate scratch: [BQ][FEND], supports BQ up to 4096
__device__ float g_gate[4096 * FEND];

// ---------------------------------------------------------------------------
// packed f32x2 helpers
// ---------------------------------------------------------------------------
__device__ __forceinline__ void fma2(unsigned long long& d,
                                     unsigned long long a,
                                     unsigned long long b) {
    asm("fma.rn.f32x2 %0, %1, %2, %0;" : "+l"(d) : "l"(a), "l"(b));
}
__device__ __forceinline__ unsigned long long pack2(float x) {
    unsigned long long r;
    asm("mov.b64 %0, {%1, %1};" : "=l"(r) : "f"(x));
    return r;
}
__device__ __forceinline__ float2 unpack2(unsigned long long v) {
    float2 r;
    asm("mov.b64 {%0, %1}, %2;" : "=f"(r.x), "=f"(r.y) : "l"(v));
    return r;
}

// ---------------------------------------------------------------------------
// Kernel 1: per-query cosine scores over 20 keys, top-10, softmax -> dense gate
// Block = one query, 640 threads = 20 warps (warp w handles key k = w).
// ---------------------------------------------------------------------------
__global__ void scores_gate_kernel(const float* __restrict__ x,
                                   const float* __restrict__ K,
                                   const float* __restrict__ A) {
    __shared__ float x_s[KEY_D];
    __shared__ float sc[FEND];

    const int bq  = blockIdx.x;
    const int tid = threadIdx.x;

    // stage the query row
    const float4* xr4 = (const float4*)(x + (size_t)bq * KEY_D);
    for (int i = tid; i < KEY_D / 4; i += blockDim.x)
        ((float4*)x_s)[i] = xr4[i];
    __syncthreads();

    const int w    = tid >> 5;
    const int lane = tid & 31;

    if (w < FEND) {
        const float4* Ar  = (const float4*)(A + (size_t)w * KEY_D);
        const float4* Kr  = (const float4*)(K + (size_t)w * KEY_D);
        const float4* xs4 = (const float4*)x_s;
        float dot = 0.f, na = 0.f, nk = 0.f;
#pragma unroll
        for (int i = 0; i < KEY_D / 4 / 32; ++i) {   // 6 iters
            int idx = lane + i * 32;
            float4 xa = xs4[idx];
            float4 aa = Ar[idx];
            float4 kk = Kr[idx];
            float t;
            t = xa.x * aa.x; dot = fmaf(t, kk.x, dot); na = fmaf(t, t, na); nk = fmaf(kk.x, kk.x, nk);
            t = xa.y * aa.y; dot = fmaf(t, kk.y, dot); na = fmaf(t, t, na); nk = fmaf(kk.y, kk.y, nk);
            t = xa.z * aa.z; dot = fmaf(t, kk.z, dot); na = fmaf(t, t, na); nk = fmaf(kk.z, kk.z, nk);
            t = xa.w * aa.w; dot = fmaf(t, kk.w, dot); na = fmaf(t, t, na); nk = fmaf(kk.w, kk.w, nk);
        }
#pragma unroll
        for (int off = 16; off; off >>= 1) {
            dot += __shfl_xor_sync(0xFFFFFFFFu, dot, off);
            na  += __shfl_xor_sync(0xFFFFFFFFu, na,  off);
            nk  += __shfl_xor_sync(0xFFFFFFFFu, nk,  off);
        }
        if (lane == 0) {
            float nq = fmaxf(sqrtf(na), EPSV);
            float nK = fmaxf(sqrtf(nk), EPSV);
            sc[w] = dot / (nq * nK);
        }
    }
    __syncthreads();

    if (tid == 0) {
        float s[FEND];
#pragma unroll
        for (int k = 0; k < FEND; ++k) s[k] = sc[k];
        float tv[TOPKN]; int ti[TOPKN];
#pragma unroll
        for (int j = 0; j < TOPKN; ++j) {
            int bi = 0; float bv = -__int_as_float(0x7F800000); // -inf
#pragma unroll
            for (int k = 0; k < FEND; ++k)
                if (s[k] > bv) { bv = s[k]; bi = k; }
            tv[j] = bv; ti[j] = bi;
            s[bi] = -__int_as_float(0x7F800000);
        }
        float m = tv[0], sum = 0.f;
        float e[TOPKN];
#pragma unroll
        for (int j = 0; j < TOPKN; ++j) { e[j] = __expf(tv[j] - m); sum += e[j]; }
        float inv = 1.f / sum;
        float* gr = g_gate + (size_t)bq * FEND;
#pragma unroll
        for (int k = 0; k < FEND; ++k) gr[k] = 0.f;
#pragma unroll
        for (int j = 0; j < TOPKN; ++j) gr[ti[j]] = e[j] * inv;
    }
}

// ---------------------------------------------------------------------------
// Kernel 2: out[bq,l,d] = sum_k gate[bq,k] * p[k,l,d]   (dense K=20 mini-GEMM)
// Grid: (D/DC, 8, BQ/QB).  Block: 256 threads.
// Thread tile: 8 queries (paired into 4 f32x2 lanes) x 4 d (one float4).
// p tile + gate tile staged in smem; accumulation via fma.rn.f32x2.
// Output split: l<4 -> Ek half, l>=4 -> Ev half.
// ---------------------------------------------------------------------------
__global__ __launch_bounds__(K2_THREADS)
void expand_kernel(const float* __restrict__ p,
                   float* __restrict__ out,
                   int BQ) {
    __shared__ float ps_s[FEND * DC];   // [k][128]
    __shared__ float gt_s[FEND * QB];   // [k][64]

    const int d0  = blockIdx.x * DC;
    const int l   = blockIdx.y;
    const int q0  = blockIdx.z * QB;
    const int tid = threadIdx.x;

    // stage p tile: rows k, columns d0..d0+127 of plane (k, l)
    for (int i = tid; i < FEND * (DC / 4); i += K2_THREADS) {
        int k = i / (DC / 4);
        int c = i % (DC / 4);
        ((float4*)ps_s)[i] =
            *(const float4*)(p + ((size_t)(k * E_P_LEN + l)) * P_FEAT + d0 + c * 4);
    }
    // stage gate tile, transposed to [k][q]
    for (int i = tid; i < FEND * QB; i += K2_THREADS) {
        int k = i / QB, q = i % QB;
        int qq = q0 + q;
        gt_s[k * QB + q] = (qq < BQ) ? g_gate[(size_t)qq * FEND + k] : 0.f;
    }
    __syncthreads();

    const int lane = tid & 31;    // d position within chunk (x4)
    const int wg   = tid >> 5;    // query group (8 queries)

    unsigned long long acc[4][4];
#pragma unroll
    for (int a = 0; a < 4; ++a)
#pragma unroll
        for (int b = 0; b < 4; ++b) acc[a][b] = 0ull;

#pragma unroll
    for (int k = 0; k < FEND; ++k) {
        float4 pv = ((const float4*)ps_s)[k * (DC / 4) + lane];
        const ulonglong2* gp =
            (const ulonglong2*)(gt_s + k * QB + wg * 8);  // 8 gates = 4 f32x2 pairs
        ulonglong2 ga = gp[0];
        ulonglong2 gb = gp[1];
        unsigned long long p0 = pack2(pv.x);
        unsigned long long p1 = pack2(pv.y);
        unsigned long long p2 = pack2(pv.z);
        unsigned long long p3 = pack2(pv.w);
        fma2(acc[0][0], ga.x, p0); fma2(acc[0][1], ga.x, p1);
        fma2(acc[0][2], ga.x, p2); fma2(acc[0][3], ga.x, p3);
        fma2(acc[1][0], ga.y, p0); fma2(acc[1][1], ga.y, p1);
        fma2(acc[1][2], ga.y, p2); fma2(acc[1][3], ga.y, p3);
        fma2(acc[2][0], gb.x, p0); fma2(acc[2][1], gb.x, p1);
        fma2(acc[2][2], gb.x, p2); fma2(acc[2][3], gb.x, p3);
        fma2(acc[3][0], gb.y, p0); fma2(acc[3][1], gb.y, p1);
        fma2(acc[3][2], gb.y, p2); fma2(acc[3][3], gb.y, p3);
    }

    // writeout: Ek = rows [0, BQ*4), Ev = rows [BQ*4, BQ*8)
    const size_t halfrows = (size_t)BQ * 4;
    const int dcol = d0 + lane * 4;
#pragma unroll
    for (int qp = 0; qp < 4; ++qp) {
        float2 u0 = unpack2(acc[qp][0]);
        float2 u1 = unpack2(acc[qp][1]);
        float2 u2 = unpack2(acc[qp][2]);
        float2 u3 = unpack2(acc[qp][3]);
        int q = q0 + wg * 8 + qp * 2;
        if (q + 1 < BQ || q < BQ) {
            size_t row0 = (l < 4) ? ((size_t)q * 4 + l)
                                  : (halfrows + (size_t)q * 4 + (l - 4));
            size_t row1 = (l < 4) ? ((size_t)(q + 1) * 4 + l)
                                  : (halfrows + (size_t)(q + 1) * 4 + (l - 4));
            float4 o0 = make_float4(u0.x, u1.x, u2.x, u3.x);
            float4 o1 = make_float4(u0.y, u1.y, u2.y, u3.y);
            if (q < BQ)
                *(float4*)(out + row0 * P_FEAT + dcol) = o0;
            if (q + 1 < BQ)
                *(float4*)(out + row1 * P_FEAT + dcol) = o1;
        }
    }
}

// ---------------------------------------------------------------------------
// Launch
// ---------------------------------------------------------------------------
extern "C" void kernel_launch(void* const* d_in, const int* in_sizes, int n_in,
                              void* d_out, int out_size) {
    // Inputs (metadata order): x_querry, l, x_block, K, A, p.
    // Detect whether the scalar 'l' is present (size-1 input at slot 1).
    int iK, iA, ip;
    if (n_in >= 6 && in_sizes[1] == 1) { iK = 3; iA = 4; ip = 5; }
    else                               { iK = 2; iA = 3; ip = 4; }

    const float* x = (const float*)d_in[0];
    const float* K = (const float*)d_in[iK];
    const float* A = (const float*)d_in[iA];
    const float* p = (const float*)d_in[ip];
    float*     out = (float*)d_out;

    const int BQ = in_sizes[0] / KEY_D;   // 1024 for (4, 256)

    scores_gate_kernel<<<BQ, 640>>>(x, K, A);

    dim3 grid(P_FEAT / DC, E_P_LEN, (BQ + QB - 1) / QB);
    expand_kernel<<<grid, K2_THREADS>>>(p, out, BQ);
}

// round 3
// speedup vs baseline: 1.2084x; 1.2084x over previous
#include <cuda_runtime.h>
#include <cstdint>

// Problem constants (fixed by reference: POOL=100, N_TASKS=5 -> F_END=20)
#define KEY_D   768
#define EMB_D   768
#define P_FEAT  9216      // EMB_D * HEADS
#define E_P_LEN 8
#define FEND    20
#define TOPKN   10
#define EPSV    1e-12f

// Kernel-1 tiling
#define QPB 8             // queries per block (K/A rows register-resident per warp)
#define K1_THREADS 640    // 20 warps, warp w <-> key w

// Kernel-2 tiling
#define DC  128           // d-chunk per block
#define QB  64            // queries per block
#define K2_THREADS 256    // 8 query-groups (warps) x 32 d-lanes

// Dense gate scratch: [BQ][FEND], supports BQ up to 4096
__device__ float g_gate[4096 * FEND];

// ---------------------------------------------------------------------------
// packed f32x2 helpers
// ---------------------------------------------------------------------------
__device__ __forceinline__ void fma2(unsigned long long& d,
                                     unsigned long long a,
                                     unsigned long long b) {
    asm("fma.rn.f32x2 %0, %1, %2, %0;" : "+l"(d) : "l"(a), "l"(b));
}
__device__ __forceinline__ unsigned long long pack2(float x) {
    unsigned long long r;
    asm("mov.b64 %0, {%1, %1};" : "=l"(r) : "f"(x));
    return r;
}
__device__ __forceinline__ float2 unpack2(unsigned long long v) {
    float2 r;
    asm("mov.b64 {%0, %1}, %2;" : "=f"(r.x), "=f"(r.y) : "l"(v));
    return r;
}

// ---------------------------------------------------------------------------
// Kernel 1 (v2): 8 queries per block, 20 warps (one per key).
// Each warp holds its A/K rows in REGISTERS (48 floats/lane) and loops the
// 8 staged query rows from smem -> K/A global traffic cut 8x vs v1.
// Then thread t<8 does the serial top-10 + softmax for query q0+t.
// ---------------------------------------------------------------------------
__global__ __launch_bounds__(K1_THREADS)
void scores_gate_kernel(const float* __restrict__ x,
                        const float* __restrict__ K,
                        const float* __restrict__ A,
                        int BQ) {
    __shared__ float x_s[QPB][KEY_D];   // 24 KB
    __shared__ float sc[QPB][FEND];

    const int q0  = blockIdx.x * QPB;
    const int tid = threadIdx.x;
    const int w   = tid >> 5;           // key index (0..19)
    const int lane = tid & 31;

    // stage QPB query rows
    {
        const float4* src = (const float4*)(x + (size_t)q0 * KEY_D);
        for (int i = tid; i < QPB * KEY_D / 4; i += K1_THREADS)
            ((float4*)&x_s[0][0])[i] = src[i];
    }
    __syncthreads();

    // load this warp's A/K rows into registers
    float4 a6[6], k6[6];
    {
        const float4* Ar = (const float4*)(A + (size_t)w * KEY_D);
        const float4* Kr = (const float4*)(K + (size_t)w * KEY_D);
#pragma unroll
        for (int i = 0; i < 6; ++i) {
            a6[i] = Ar[lane + 32 * i];
            k6[i] = Kr[lane + 32 * i];
        }
    }
    // key norm (computed once per warp)
    float nk = 0.f;
#pragma unroll
    for (int i = 0; i < 6; ++i) {
        nk = fmaf(k6[i].x, k6[i].x, nk);
        nk = fmaf(k6[i].y, k6[i].y, nk);
        nk = fmaf(k6[i].z, k6[i].z, nk);
        nk = fmaf(k6[i].w, k6[i].w, nk);
    }
#pragma unroll
    for (int off = 16; off; off >>= 1)
        nk += __shfl_xor_sync(0xFFFFFFFFu, nk, off);
    const float nKc = fmaxf(sqrtf(nk), EPSV);

    // loop over the 8 queries
#pragma unroll
    for (int q = 0; q < QPB; ++q) {
        const float4* xs4 = (const float4*)x_s[q];
        float dot = 0.f, na = 0.f;
#pragma unroll
        for (int i = 0; i < 6; ++i) {
            float4 xa = xs4[lane + 32 * i];
            float t;
            t = xa.x * a6[i].x; dot = fmaf(t, k6[i].x, dot); na = fmaf(t, t, na);
            t = xa.y * a6[i].y; dot = fmaf(t, k6[i].y, dot); na = fmaf(t, t, na);
            t = xa.z * a6[i].z; dot = fmaf(t, k6[i].z, dot); na = fmaf(t, t, na);
            t = xa.w * a6[i].w; dot = fmaf(t, k6[i].w, dot); na = fmaf(t, t, na);
        }
#pragma unroll
        for (int off = 16; off; off >>= 1) {
            dot += __shfl_xor_sync(0xFFFFFFFFu, dot, off);
            na  += __shfl_xor_sync(0xFFFFFFFFu, na,  off);
        }
        if (lane == 0)
            sc[q][w] = dot / (fmaxf(sqrtf(na), EPSV) * nKc);
    }
    __syncthreads();

    // top-10 + softmax -> dense gate (one thread per query)
    if (tid < QPB && q0 + tid < BQ) {
        float s[FEND];
#pragma unroll
        for (int k = 0; k < FEND; ++k) s[k] = sc[tid][k];
        float tv[TOPKN]; int ti[TOPKN];
#pragma unroll
        for (int j = 0; j < TOPKN; ++j) {
            int bi = 0; float bv = -__int_as_float(0x7F800000); // -inf
#pragma unroll
            for (int k = 0; k < FEND; ++k)
                if (s[k] > bv) { bv = s[k]; bi = k; }
            tv[j] = bv; ti[j] = bi;
            s[bi] = -__int_as_float(0x7F800000);
        }
        float m = tv[0], sum = 0.f;
        float e[TOPKN];
#pragma unroll
        for (int j = 0; j < TOPKN; ++j) { e[j] = __expf(tv[j] - m); sum += e[j]; }
        float inv = 1.f / sum;
        float* gr = g_gate + (size_t)(q0 + tid) * FEND;
#pragma unroll
        for (int k = 0; k < FEND; ++k) gr[k] = 0.f;
#pragma unroll
        for (int j = 0; j < TOPKN; ++j) gr[ti[j]] = e[j] * inv;
    }
}

// ---------------------------------------------------------------------------
// Kernel 2: out[bq,l,d] = sum_k gate[bq,k] * p[k,l,d]   (dense K=20 mini-GEMM)
// Grid: (D/DC, 8, BQ/QB).  Block: 256 threads, 4 CTAs/SM forced (regs <= 64).
// Thread tile: 8 queries (paired into 4 f32x2 lanes) x 4 d (one float4).
// ---------------------------------------------------------------------------
__global__ __launch_bounds__(K2_THREADS, 4)
void expand_kernel(const float* __restrict__ p,
                   float* __restrict__ out,
                   int BQ) {
    __shared__ float ps_s[FEND * DC];   // [k][128]  10 KB
    __shared__ float gt_s[FEND * QB];   // [k][64]    5 KB

    const int d0  = blockIdx.x * DC;
    const int l   = blockIdx.y;
    const int q0  = blockIdx.z * QB;
    const int tid = threadIdx.x;

    // stage p tile: rows k, columns d0..d0+127 of plane (k, l)
    for (int i = tid; i < FEND * (DC / 4); i += K2_THREADS) {
        int k = i / (DC / 4);
        int c = i % (DC / 4);
        ((float4*)ps_s)[i] =
            *(const float4*)(p + ((size_t)(k * E_P_LEN + l)) * P_FEAT + d0 + c * 4);
    }
    // stage gate tile, transposed to [k][q]
    for (int i = tid; i < FEND * QB; i += K2_THREADS) {
        int k = i / QB, q = i % QB;
        int qq = q0 + q;
        gt_s[k * QB + q] = (qq < BQ) ? g_gate[(size_t)qq * FEND + k] : 0.f;
    }
    __syncthreads();

    const int lane = tid & 31;    // d position within chunk (x4)
    const int wg   = tid >> 5;    // query group (8 queries)

    unsigned long long acc[4][4];
#pragma unroll
    for (int a = 0; a < 4; ++a)
#pragma unroll
        for (int b = 0; b < 4; ++b) acc[a][b] = 0ull;

#pragma unroll
    for (int k = 0; k < FEND; ++k) {
        float4 pv = ((const float4*)ps_s)[k * (DC / 4) + lane];
        const ulonglong2* gp =
            (const ulonglong2*)(gt_s + k * QB + wg * 8);  // 8 gates = 4 f32x2 pairs
        ulonglong2 ga = gp[0];
        ulonglong2 gb = gp[1];
        unsigned long long p0 = pack2(pv.x);
        unsigned long long p1 = pack2(pv.y);
        unsigned long long p2 = pack2(pv.z);
        unsigned long long p3 = pack2(pv.w);
        fma2(acc[0][0], ga.x, p0); fma2(acc[0][1], ga.x, p1);
        fma2(acc[0][2], ga.x, p2); fma2(acc[0][3], ga.x, p3);
        fma2(acc[1][0], ga.y, p0); fma2(acc[1][1], ga.y, p1);
        fma2(acc[1][2], ga.y, p2); fma2(acc[1][3], ga.y, p3);
        fma2(acc[2][0], gb.x, p0); fma2(acc[2][1], gb.x, p1);
        fma2(acc[2][2], gb.x, p2); fma2(acc[2][3], gb.x, p3);
        fma2(acc[3][0], gb.y, p0); fma2(acc[3][1], gb.y, p1);
        fma2(acc[3][2], gb.y, p2); fma2(acc[3][3], gb.y, p3);
    }

    // writeout: Ek = rows [0, BQ*4), Ev = rows [BQ*4, BQ*8)
    const size_t halfrows = (size_t)BQ * 4;
    const int dcol = d0 + lane * 4;
    const int lrow = (l < 4) ? l : (l - 4);
    const size_t base = (l < 4) ? 0 : halfrows;
#pragma unroll
    for (int qp = 0; qp < 4; ++qp) {
        float2 u0 = unpack2(acc[qp][0]);
        float2 u1 = unpack2(acc[qp][1]);
        float2 u2 = unpack2(acc[qp][2]);
        float2 u3 = unpack2(acc[qp][3]);
        int q = q0 + wg * 8 + qp * 2;
        size_t row0 = base + (size_t)q * 4 + lrow;
        size_t row1 = base + (size_t)(q + 1) * 4 + lrow;
        float4 o0 = make_float4(u0.x, u1.x, u2.x, u3.x);
        float4 o1 = make_float4(u0.y, u1.y, u2.y, u3.y);
        if (q < BQ)
            *(float4*)(out + row0 * P_FEAT + dcol) = o0;
        if (q + 1 < BQ)
            *(float4*)(out + row1 * P_FEAT + dcol) = o1;
    }
}

// ---------------------------------------------------------------------------
// Launch
// ---------------------------------------------------------------------------
extern "C" void kernel_launch(void* const* d_in, const int* in_sizes, int n_in,
                              void* d_out, int out_size) {
    // Inputs (metadata order): x_querry, l, x_block, K, A, p.
    // Detect whether the scalar 'l' is present (size-1 input at slot 1).
    int iK, iA, ip;
    if (n_in >= 6 && in_sizes[1] == 1) { iK = 3; iA = 4; ip = 5; }
    else                               { iK = 2; iA = 3; ip = 4; }

    const float* x = (const float*)d_in[0];
    const float* K = (const float*)d_in[iK];
    const float* A = (const float*)d_in[iA];
    const float* p = (const float*)d_in[ip];
    float*     out = (float*)d_out;

    const int BQ = in_sizes[0] / KEY_D;   // 1024 for (4, 256)

    scores_gate_kernel<<<(BQ + QPB - 1) / QPB, K1_THREADS>>>(x, K, A, BQ);

    dim3 grid(P_FEAT / DC, E_P_LEN, (BQ + QB - 1) / QB);
    expand_kernel<<<grid, K2_THREADS>>>(p, out, BQ);
}